// round 10
// baseline (speedup 1.0000x reference)
#include <cuda_runtime.h>
#include <cuda_fp16.h>
#include <cstdint>

#define BB    64
#define TT    512
#define DIN   512
#define DHID  1024
#define DOUT  512
#define NDAYS 24
#define EPS_  1e-5f

// Scratch (__device__ globals; no runtime allocation).
__device__ __half g_xh [(size_t)BB * TT * DIN];       // 32 MB x -> fp16
__device__ __half g_h  [(size_t)BB * TT * DHID];      // 64 MB hidden fp16
__device__ __half g_wt1[(size_t)NDAYS * DHID * DIN];  // 24 MB W1^T [d][n][k] fp16
__device__ __half g_wt2[(size_t)NDAYS * DOUT * DHID]; // 24 MB W2^T [d][n][k] fp16

// ---------------------------------------------------------------- helpers
__device__ __forceinline__ uint32_t smem_u32(const void* p) {
    uint32_t a;
    asm("{ .reg .u64 t; cvta.to.shared.u64 t, %1; cvt.u32.u64 %0, t; }"
        : "=r"(a) : "l"(p));
    return a;
}
__device__ __forceinline__ void cp16(uint32_t dst, const void* src) {
    asm volatile("cp.async.cg.shared.global [%0], [%1], 16;"
                 :: "r"(dst), "l"(src) : "memory");
}
__device__ __forceinline__ void ldm4(uint32_t& r0, uint32_t& r1,
                                     uint32_t& r2, uint32_t& r3, uint32_t a) {
    asm volatile("ldmatrix.sync.aligned.m8n8.x4.shared.b16 {%0,%1,%2,%3}, [%4];"
                 : "=r"(r0), "=r"(r1), "=r"(r2), "=r"(r3) : "r"(a));
}
__device__ __forceinline__ void mma16816(float* c, const uint32_t* a,
                                         uint32_t b0, uint32_t b1) {
    asm volatile(
        "mma.sync.aligned.m16n8k16.row.col.f32.f16.f16.f32 "
        "{%0,%1,%2,%3}, {%4,%5,%6,%7}, {%8,%9}, {%0,%1,%2,%3};"
        : "+f"(c[0]), "+f"(c[1]), "+f"(c[2]), "+f"(c[3])
        : "r"(a[0]), "r"(a[1]), "r"(a[2]), "r"(a[3]), "r"(b0), "r"(b1));
}

// ---------------------------------------------------------------- fused prep
template<int K, int N>
__device__ __forceinline__ void transpose_tile(const float* __restrict__ W,
                                               __half* __restrict__ Wt,
                                               int d, int n0, int k0,
                                               float (*t)[33], int tx, int ty) {
    const float* Wd  = W  + (size_t)d * K * N;
    __half*      Wtd = Wt + (size_t)d * N * K;
    #pragma unroll
    for (int r = 0; r < 32; r += 8)
        t[ty + r][tx] = Wd[(size_t)(k0 + ty + r) * N + n0 + tx];
    __syncthreads();
    #pragma unroll
    for (int r = 0; r < 32; r += 8)
        Wtd[(size_t)(n0 + ty + r) * K + k0 + tx] = __float2half_rn(t[tx][ty + r]);
}

#define NBLK_X  8192
#define NBLK_W1 (32 * 16 * NDAYS)
#define NBLK_W2 (16 * 32 * NDAYS)

__global__ __launch_bounds__(256) void prep_kernel(
    const float4* __restrict__ x, __half2* __restrict__ xh,
    const float* __restrict__ W1, __half* __restrict__ wt1,
    const float* __restrict__ W2, __half* __restrict__ wt2)
{
    __shared__ float t[32][33];
    const int blk = blockIdx.x;
    const int tid = threadIdx.x;
    if (blk < NBLK_X) {
        const int i = blk * 256 + tid;
        float4 v0 = x[i * 2], v1 = x[i * 2 + 1];
        xh[i * 4 + 0] = __floats2half2_rn(v0.x, v0.y);
        xh[i * 4 + 1] = __floats2half2_rn(v0.z, v0.w);
        xh[i * 4 + 2] = __floats2half2_rn(v1.x, v1.y);
        xh[i * 4 + 3] = __floats2half2_rn(v1.z, v1.w);
    } else if (blk < NBLK_X + NBLK_W1) {
        int r = blk - NBLK_X;
        const int d = r / (32 * 16); r %= 32 * 16;
        const int n0 = (r % 32) * 32;
        const int k0 = (r / 32) * 32;
        transpose_tile<DIN, DHID>(W1, wt1, d, n0, k0, t, tid & 31, tid >> 5);
    } else {
        int r = blk - NBLK_X - NBLK_W1;
        const int d = r / (16 * 32); r %= 16 * 32;
        const int n0 = (r % 16) * 32;
        const int k0 = (r / 16) * 32;
        transpose_tile<DHID, DOUT>(W2, wt2, d, n0, k0, t, tid & 31, tid >> 5);
    }
}

// ---------------------------------------------------------------- GEMM1 (= R8)
#define STAGES 3
#define STAGE_BYTES 32768
#define SMEM_DYN (STAGES * STAGE_BYTES)

template<int KDIM, int NTOT, bool RELU, typename CT>
__global__ __launch_bounds__(256, 2) void gemm_mma(
    const __half* __restrict__ A,
    const __half* __restrict__ Wt,
    const float*  __restrict__ bias,
    const int*    __restrict__ day,
    CT*           __restrict__ C)
{
    extern __shared__ char smem[];
    const uint32_t sbase = smem_u32(smem);

    const int tid  = threadIdx.x;
    const int lane = tid & 31;
    const int wid  = tid >> 5;
    const int wm   = wid & 1;
    const int wn   = wid >> 1;

    const int b  = blockIdx.x;
    const int m0 = blockIdx.y * 128;
    const int n0 = blockIdx.z * 128;
    const int d  = __ldg(day + b);

    const __half* Arow = A  + (size_t)(b * TT + m0) * KDIM;
    const __half* Brow = Wt + ((size_t)d * NTOT + n0) * KDIM;

    const int lrow = tid >> 3;
    const int lchk = tid & 7;

    constexpr int KT = KDIM / 64;

    auto cp_part = [&](int s, int kt, int p) {
        const uint32_t as_ = sbase + s * STAGE_BYTES;
        const int row = p * 32 + lrow;
        const uint32_t soff = row * 128 + ((lchk ^ (row & 7)) << 4);
        const size_t goff = (size_t)kt * 64 + (size_t)row * KDIM + lchk * 8;
        cp16(as_ + soff,         Arow + goff);
        cp16(as_ + 16384 + soff, Brow + goff);
    };
    auto cp_stage = [&](int s, int kt) {
        #pragma unroll
        for (int p = 0; p < 4; p++) cp_part(s, kt, p);
        asm volatile("cp.async.commit_group;" ::: "memory");
    };

    const int lrow16 = lane & 15;
    const int lhi    = lane >> 4;
    auto load_afr = [&](uint32_t as_, int ks, uint32_t (*f)[4]) {
        const int chk = 2 * ks + lhi;
        #pragma unroll
        for (int mt = 0; mt < 4; mt++) {
            const int row = wm * 64 + mt * 16 + lrow16;
            ldm4(f[mt][0], f[mt][1], f[mt][2], f[mt][3],
                 as_ + row * 128 + (((row & 7) ^ chk) << 4));
        }
    };
    auto load_bfr = [&](uint32_t bs_, int ks, uint32_t (*f)[4]) {
        const int chk = 2 * ks + lhi;
        #pragma unroll
        for (int p = 0; p < 2; p++) {
            const int row = wn * 32 + p * 16 + lrow16;
            ldm4(f[p][0], f[p][1], f[p][2], f[p][3],
                 bs_ + row * 128 + (((row & 7) ^ chk) << 4));
        }
    };

    cp_stage(0, 0);
    cp_stage(1, 1);
    asm volatile("cp.async.wait_group 1;" ::: "memory");
    __syncthreads();

    float acc[4][4][4] = {};
    uint32_t af[2][4][4], bf[2][2][4];
    load_afr(sbase, 0, af[0]);
    load_bfr(sbase + 16384, 0, bf[0]);

    for (int i = 0; i < KT; i++) {
        const uint32_t as = sbase + (i % STAGES) * STAGE_BYTES;
        const uint32_t bs = as + 16384;
        const int inext = i + 2;
        const int snext = inext % STAGES;

        #pragma unroll
        for (int ks = 0; ks < 4; ks++) {
            const int cur = ks & 1, nxt = cur ^ 1;

            if (ks < 3) {
                load_afr(as, ks + 1, af[nxt]);
                load_bfr(bs, ks + 1, bf[nxt]);
            }
            if (inext < KT) cp_part(snext, inext, ks);

            if (ks == 2 && i + 1 < KT) {
                asm volatile("cp.async.wait_group 0;" ::: "memory");
                __syncthreads();
            }
            if (ks == 3) {
                if (inext < KT)
                    asm volatile("cp.async.commit_group;" ::: "memory");
                if (i + 1 < KT) {
                    const uint32_t as2 = sbase + ((i + 1) % STAGES) * STAGE_BYTES;
                    load_afr(as2, 0, af[nxt]);
                    load_bfr(as2 + 16384, 0, bf[nxt]);
                }
            }

            #pragma unroll
            for (int mt = 0; mt < 4; mt++)
                #pragma unroll
                for (int nt = 0; nt < 4; nt++)
                    mma16816(acc[mt][nt], af[cur][mt],
                             bf[cur][nt >> 1][nt & 1], bf[cur][nt >> 1][2 + (nt & 1)]);
        }
    }

    const int g   = lane >> 2;
    const int tig = lane & 3;
    const float* biasd = bias + (size_t)d * NTOT + n0 + wn * 32;
    CT* Cb = C + (size_t)(b * TT + m0 + wm * 64) * NTOT + n0 + wn * 32;

    #pragma unroll
    for (int nt = 0; nt < 4; nt++) {
        const int coff = nt * 8 + tig * 2;
        const float2 bb = *(const float2*)(biasd + coff);
        #pragma unroll
        for (int mt = 0; mt < 4; mt++) {
            const int r0 = mt * 16 + g;
            float2 v0, v1;
            v0.x = acc[mt][nt][0] + bb.x;  v0.y = acc[mt][nt][1] + bb.y;
            v1.x = acc[mt][nt][2] + bb.x;  v1.y = acc[mt][nt][3] + bb.y;
            if (RELU) {
                v0.x = fmaxf(v0.x, 0.0f); v0.y = fmaxf(v0.y, 0.0f);
                v1.x = fmaxf(v1.x, 0.0f); v1.y = fmaxf(v1.y, 0.0f);
            }
            if constexpr (sizeof(CT) == 2) {
                *(__half2*)((__half*)Cb + (size_t)r0 * NTOT + coff) =
                    __floats2half2_rn(v0.x, v0.y);
                *(__half2*)((__half*)Cb + (size_t)(r0 + 8) * NTOT + coff) =
                    __floats2half2_rn(v1.x, v1.y);
            } else {
                *(float2*)((float*)Cb + (size_t)r0 * NTOT + coff)       = v0;
                *(float2*)((float*)Cb + (size_t)(r0 + 8) * NTOT + coff) = v1;
            }
        }
    }
}

// ---------------------------------------------------------------- GEMM2 + LN fused
// CTA = 64 rows x 512 cols (full D_OUT). 512 threads, 16 warps 2(M) x 8(N);
// warp tile 32x64. K-chunk 64, KT=16, 3 stages. LayerNorm in epilogue via
// 4KB smem cross-warp reduction. 1 CTA/SM (216KB smem), 16 warps/SM.
#define A2_BYTES 8192                          // 64 rows x 128B
#define B2_BYTES 65536                         // 512 rows x 128B
#define STAGE2_BYTES (A2_BYTES + B2_BYTES)     // 73728
#define SMEM2_DYN (3 * STAGE2_BYTES)           // 221184

__global__ __launch_bounds__(512, 1) void gemm2_ln(
    const __half* __restrict__ A,     // h  [BB*TT, DHID]
    const __half* __restrict__ Wt,    // W2^T [NDAYS, DOUT, DHID]
    const float*  __restrict__ bias,  // b2 [NDAYS, DOUT]
    const float*  __restrict__ gamma,
    const float*  __restrict__ beta,
    const int*    __restrict__ day,
    float*        __restrict__ out)
{
    extern __shared__ char smem[];
    const uint32_t sbase = smem_u32(smem);

    const int tid  = threadIdx.x;
    const int lane = tid & 31;
    const int wid  = tid >> 5;     // 0..15
    const int wm   = wid & 1;      // rows wm*32
    const int wn   = wid >> 1;     // cols wn*64

    const int b  = blockIdx.x;
    const int m0 = blockIdx.y * 64;
    const int d  = __ldg(day + b);

    const __half* Arow = A  + (size_t)(b * TT + m0) * DHID;
    const __half* Brow = Wt + (size_t)d * DOUT * DHID;

    constexpr int KT = DHID / 64;   // 16

    // 576 tile rows (64 A + 512 B) x 8 chunks = 4608 cp16 = 9 per thread.
    auto cp_stage = [&](int s, int kt) {
        const uint32_t st = sbase + s * STAGE2_BYTES;
        #pragma unroll
        for (int j = 0; j < 9; j++) {
            const int c   = j * 512 + tid;
            const int row = c >> 3;
            const int chk = c & 7;
            if (row < 64) {
                const uint32_t soff = row * 128 + ((chk ^ (row & 7)) << 4);
                cp16(st + soff,
                     Arow + (size_t)kt * 64 + (size_t)row * DHID + chk * 8);
            } else {
                const int r2 = row - 64;
                const uint32_t soff = r2 * 128 + ((chk ^ (r2 & 7)) << 4);
                cp16(st + A2_BYTES + soff,
                     Brow + (size_t)kt * 64 + (size_t)r2 * DHID + chk * 8);
            }
        }
        asm volatile("cp.async.commit_group;" ::: "memory");
    };

    const int lrow16 = lane & 15;
    const int lhi    = lane >> 4;
    auto load_afr = [&](uint32_t st, int ks, uint32_t (*f)[4]) {
        const int chk = 2 * ks + lhi;
        #pragma unroll
        for (int mt = 0; mt < 2; mt++) {
            const int row = wm * 32 + mt * 16 + lrow16;
            ldm4(f[mt][0], f[mt][1], f[mt][2], f[mt][3],
                 st + row * 128 + (((row & 7) ^ chk) << 4));
        }
    };
    auto load_bfr = [&](uint32_t st, int ks, uint32_t (*f)[4]) {
        const int chk = 2 * ks + lhi;
        #pragma unroll
        for (int p = 0; p < 4; p++) {
            const int row = wn * 64 + p * 16 + lrow16;
            ldm4(f[p][0], f[p][1], f[p][2], f[p][3],
                 st + A2_BYTES + row * 128 + (((row & 7) ^ chk) << 4));
        }
    };

    cp_stage(0, 0);
    cp_stage(1, 1);
    asm volatile("cp.async.wait_group 1;" ::: "memory");
    __syncthreads();

    float acc[2][8][4] = {};
    uint32_t af[2][2][4], bf[2][4][4];
    load_afr(sbase, 0, af[0]);
    load_bfr(sbase, 0, bf[0]);

    for (int i = 0; i < KT; i++) {
        const uint32_t st = sbase + (i % 3) * STAGE2_BYTES;

        #pragma unroll
        for (int ks = 0; ks < 4; ks++) {
            const int cur = ks & 1, nxt = cur ^ 1;

            if (ks == 0 && i + 2 < KT) cp_stage((i + 2) % 3, i + 2);

            if (ks < 3) {
                load_afr(st, ks + 1, af[nxt]);
                load_bfr(st, ks + 1, bf[nxt]);
            }
            if (ks == 2 && i + 1 < KT) {
                // need stage i+1 resident before ks==3 frag prefetch
                if (i + 2 < KT)
                    asm volatile("cp.async.wait_group 1;" ::: "memory");
                else
                    asm volatile("cp.async.wait_group 0;" ::: "memory");
                __syncthreads();
            }
            if (ks == 3 && i + 1 < KT) {
                const uint32_t st2 = sbase + ((i + 1) % 3) * STAGE2_BYTES;
                load_afr(st2, 0, af[nxt]);
                load_bfr(st2, 0, bf[nxt]);
            }

            #pragma unroll
            for (int mt = 0; mt < 2; mt++)
                #pragma unroll
                for (int nt = 0; nt < 8; nt++)
                    mma16816(acc[mt][nt], af[cur][mt],
                             bf[cur][nt >> 1][nt & 1], bf[cur][nt >> 1][2 + (nt & 1)]);
        }
    }

    // ---------------- fused epilogue: bias + LayerNorm + affine ----------------
    __syncthreads();                       // stage buffers free for reuse
    float2* red = (float2*)smem;           // [8 wn][64 rows] (sum, sq) = 4KB

    const int g   = lane >> 2;
    const int tig = lane & 3;
    const float* bp = bias + (size_t)d * DOUT + wn * 64;

    float s[2][2] = {}, q[2][2] = {};      // [mt][lo/hi]
    #pragma unroll
    for (int nt = 0; nt < 8; nt++) {
        const int coff = nt * 8 + tig * 2;
        const float2 bb = *(const float2*)(bp + coff);
        #pragma unroll
        for (int mt = 0; mt < 2; mt++) {
            acc[mt][nt][0] += bb.x;  acc[mt][nt][1] += bb.y;
            acc[mt][nt][2] += bb.x;  acc[mt][nt][3] += bb.y;
            s[mt][0] += acc[mt][nt][0] + acc[mt][nt][1];
            q[mt][0] += acc[mt][nt][0] * acc[mt][nt][0]
                      + acc[mt][nt][1] * acc[mt][nt][1];
            s[mt][1] += acc[mt][nt][2] + acc[mt][nt][3];
            q[mt][1] += acc[mt][nt][2] * acc[mt][nt][2]
                      + acc[mt][nt][3] * acc[mt][nt][3];
        }
    }
    #pragma unroll
    for (int off = 1; off <= 2; off <<= 1) {
        #pragma unroll
        for (int mt = 0; mt < 2; mt++)
            #pragma unroll
            for (int hh = 0; hh < 2; hh++) {
                s[mt][hh] += __shfl_xor_sync(0xffffffffu, s[mt][hh], off);
                q[mt][hh] += __shfl_xor_sync(0xffffffffu, q[mt][hh], off);
            }
    }
    if (tig == 0) {
        #pragma unroll
        for (int mt = 0; mt < 2; mt++)
            #pragma unroll
            for (int hh = 0; hh < 2; hh++) {
                const int row = wm * 32 + mt * 16 + hh * 8 + g;
                red[wn * 64 + row] = make_float2(s[mt][hh], q[mt][hh]);
            }
    }
    __syncthreads();

    float mean[2][2], inv[2][2];
    #pragma unroll
    for (int mt = 0; mt < 2; mt++)
        #pragma unroll
        for (int hh = 0; hh < 2; hh++) {
            const int row = wm * 32 + mt * 16 + hh * 8 + g;
            float ts = 0.0f, tq = 0.0f;
            #pragma unroll
            for (int w = 0; w < 8; w++) {
                const float2 r = red[w * 64 + row];
                ts += r.x;  tq += r.y;
            }
            const float mn = ts * (1.0f / DOUT);
            mean[mt][hh] = mn;
            inv[mt][hh]  = rsqrtf(tq * (1.0f / DOUT) - mn * mn + EPS_);
        }

    const float* gp = gamma + (size_t)d * DOUT + wn * 64;
    const float* zp = beta  + (size_t)d * DOUT + wn * 64;
    float* Ob = out + (size_t)(b * TT + m0 + wm * 32) * DOUT + wn * 64;

    #pragma unroll
    for (int nt = 0; nt < 8; nt++) {
        const int coff = nt * 8 + tig * 2;
        const float2 gg = *(const float2*)(gp + coff);
        const float2 zz = *(const float2*)(zp + coff);
        #pragma unroll
        for (int mt = 0; mt < 2; mt++) {
            const int rlo = mt * 16 + g;
            float2 o0, o1;
            o0.x = (acc[mt][nt][0] - mean[mt][0]) * inv[mt][0] * gg.x + zz.x;
            o0.y = (acc[mt][nt][1] - mean[mt][0]) * inv[mt][0] * gg.y + zz.y;
            o1.x = (acc[mt][nt][2] - mean[mt][1]) * inv[mt][1] * gg.x + zz.x;
            o1.y = (acc[mt][nt][3] - mean[mt][1]) * inv[mt][1] * gg.y + zz.y;
            *(float2*)(Ob + (size_t)rlo * DOUT + coff)       = o0;
            *(float2*)(Ob + (size_t)(rlo + 8) * DOUT + coff) = o1;
        }
    }
}

// ---------------------------------------------------------------- launch
extern "C" void kernel_launch(void* const* d_in, const int* in_sizes, int n_in,
                              void* d_out, int out_size)
{
    const float* x     = (const float*)d_in[0];
    const int*   day   = (const int*)  d_in[1];
    const float* W1    = (const float*)d_in[2];
    const float* b1    = (const float*)d_in[3];
    const float* W2    = (const float*)d_in[4];
    const float* b2    = (const float*)d_in[5];
    const float* gamma = (const float*)d_in[6];
    const float* beta  = (const float*)d_in[7];
    float* out = (float*)d_out;

    __half *xh, *h, *wt1, *wt2;
    cudaGetSymbolAddress((void**)&xh,  g_xh);
    cudaGetSymbolAddress((void**)&h,   g_h);
    cudaGetSymbolAddress((void**)&wt1, g_wt1);
    cudaGetSymbolAddress((void**)&wt2, g_wt2);

    prep_kernel<<<NBLK_X + NBLK_W1 + NBLK_W2, 256>>>(
        (const float4*)x, (__half2*)xh, W1, wt1, W2, wt2);

    cudaFuncSetAttribute(gemm_mma<DIN, DHID, true, __half>,
                         cudaFuncAttributeMaxDynamicSharedMemorySize, SMEM_DYN);
    cudaFuncSetAttribute(gemm2_ln,
                         cudaFuncAttributeMaxDynamicSharedMemorySize, SMEM2_DYN);

    // GEMM1: xh @ W1^T -> h (fp16, bias+relu fused)
    gemm_mma<DIN, DHID, true, __half><<<dim3(BB, TT / 128, DHID / 128), 256, SMEM_DYN>>>(
        xh, wt1, b1, day, h);
    // GEMM2 + LayerNorm fused -> out
    gemm2_ln<<<dim3(BB, TT / 64), 512, SMEM2_DYN>>>(
        h, wt2, b2, gamma, beta, day, out);
}

// round 11
// speedup vs baseline: 1.0732x; 1.0732x over previous
#include <cuda_runtime.h>
#include <cuda_fp16.h>
#include <cstdint>

#define BB    64
#define TT    512
#define DIN   512
#define DHID  1024
#define DOUT  512
#define NDAYS 24
#define EPS_  1e-5f

// Scratch (__device__ globals; no runtime allocation).
__device__ __half g_xh [(size_t)BB * TT * DIN];       // 32 MB x -> fp16
__device__ __half g_h  [(size_t)BB * TT * DHID];      // 64 MB hidden fp16
__device__ __half g_wt1[(size_t)NDAYS * DHID * DIN];  // 24 MB W1^T [d][n][k] fp16
__device__ __half g_wt2[(size_t)NDAYS * DOUT * DHID]; // 24 MB W2^T [d][n][k] fp16

// ---------------------------------------------------------------- helpers
__device__ __forceinline__ uint32_t smem_u32(const void* p) {
    uint32_t a;
    asm("{ .reg .u64 t; cvta.to.shared.u64 t, %1; cvt.u32.u64 %0, t; }"
        : "=r"(a) : "l"(p));
    return a;
}
__device__ __forceinline__ void cp16(uint32_t dst, const void* src) {
    asm volatile("cp.async.cg.shared.global [%0], [%1], 16;"
                 :: "r"(dst), "l"(src) : "memory");
}
__device__ __forceinline__ void ldm4(uint32_t& r0, uint32_t& r1,
                                     uint32_t& r2, uint32_t& r3, uint32_t a) {
    asm volatile("ldmatrix.sync.aligned.m8n8.x4.shared.b16 {%0,%1,%2,%3}, [%4];"
                 : "=r"(r0), "=r"(r1), "=r"(r2), "=r"(r3) : "r"(a));
}
__device__ __forceinline__ void mma16816(float* c, const uint32_t* a,
                                         uint32_t b0, uint32_t b1) {
    asm volatile(
        "mma.sync.aligned.m16n8k16.row.col.f32.f16.f16.f32 "
        "{%0,%1,%2,%3}, {%4,%5,%6,%7}, {%8,%9}, {%0,%1,%2,%3};"
        : "+f"(c[0]), "+f"(c[1]), "+f"(c[2]), "+f"(c[3])
        : "r"(a[0]), "r"(a[1]), "r"(a[2]), "r"(a[3]), "r"(b0), "r"(b1));
}

// ---------------------------------------------------------------- fused prep
// Transpose 32(k) x 32(n) tile of W [NDAYS][K][N] fp32 into Wt [NDAYS][N][K]
// fp16. Vectorized: float4 reads (1 LDG/thread), half2 writes along K.
template<int K, int N>
__device__ __forceinline__ void transpose_tile(const float* __restrict__ W,
                                               __half* __restrict__ Wt,
                                               int d, int n0, int k0,
                                               float (*t)[33], int tid) {
    const float* Wd  = W  + (size_t)d * K * N;
    __half*      Wtd = Wt + (size_t)d * N * K;
    {
        const int k = tid >> 3;            // 0..31
        const int c = (tid & 7) * 4;       // 0,4,..,28
        const float4 v = *(const float4*)(Wd + (size_t)(k0 + k) * N + n0 + c);
        t[k][c + 0] = v.x; t[k][c + 1] = v.y;
        t[k][c + 2] = v.z; t[k][c + 3] = v.w;
    }
    __syncthreads();
    const int k2 = (tid & 15) * 2;         // 0,2,..,30
    #pragma unroll
    for (int p = 0; p < 2; p++) {
        const int n = (tid >> 4) + p * 16; // 0..31
        const __half2 h = __floats2half2_rn(t[k2][n], t[k2 + 1][n]);
        *(__half2*)(Wtd + (size_t)(n0 + n) * K + k0 + k2) = h;
    }
}

#define NBLK_X  8192                  // (BB*TT*DIN/8)/256
#define NBLK_W1 (32 * 16 * NDAYS)     // 12288
#define NBLK_W2 (16 * 32 * NDAYS)     // 12288

__global__ __launch_bounds__(256) void prep_kernel(
    const float4* __restrict__ x, __half2* __restrict__ xh,
    const float* __restrict__ W1, __half* __restrict__ wt1,
    const float* __restrict__ W2, __half* __restrict__ wt2)
{
    __shared__ float t[32][33];
    const int blk = blockIdx.x;
    const int tid = threadIdx.x;
    if (blk < NBLK_X) {
        const int i = blk * 256 + tid;
        float4 v0 = x[i * 2], v1 = x[i * 2 + 1];
        xh[i * 4 + 0] = __floats2half2_rn(v0.x, v0.y);
        xh[i * 4 + 1] = __floats2half2_rn(v0.z, v0.w);
        xh[i * 4 + 2] = __floats2half2_rn(v1.x, v1.y);
        xh[i * 4 + 3] = __floats2half2_rn(v1.z, v1.w);
    } else if (blk < NBLK_X + NBLK_W1) {
        int r = blk - NBLK_X;
        const int d = r / (32 * 16); r %= 32 * 16;
        const int n0 = (r % 32) * 32;
        const int k0 = (r / 32) * 32;
        transpose_tile<DIN, DHID>(W1, wt1, d, n0, k0, t, tid);
    } else {
        int r = blk - NBLK_X - NBLK_W1;
        const int d = r / (16 * 32); r %= 16 * 32;
        const int n0 = (r % 16) * 32;
        const int k0 = (r / 16) * 32;
        transpose_tile<DHID, DOUT>(W2, wt2, d, n0, k0, t, tid);
    }
}

// ---------------------------------------------------------------- FP16 GEMM (= R8)
// 256 threads, 8 warps 2(M) x 4(N); warp tile 64x32; K-chunk 64; 3 stages.
// Software-pipelined frags + spread cp.async; outer chunk loop kept ROLLED
// (full unroll blows I-cache — measured R9).
#define STAGES 3
#define STAGE_BYTES 32768
#define SMEM_DYN (STAGES * STAGE_BYTES)

template<int KDIM, int NTOT, bool RELU, typename CT>
__global__ __launch_bounds__(256, 2) void gemm_mma(
    const __half* __restrict__ A,
    const __half* __restrict__ Wt,
    const float*  __restrict__ bias,
    const int*    __restrict__ day,
    CT*           __restrict__ C)
{
    extern __shared__ char smem[];
    const uint32_t sbase = smem_u32(smem);

    const int tid  = threadIdx.x;
    const int lane = tid & 31;
    const int wid  = tid >> 5;
    const int wm   = wid & 1;
    const int wn   = wid >> 1;

    const int b  = blockIdx.x;
    const int m0 = blockIdx.y * 128;
    const int n0 = blockIdx.z * 128;
    const int d  = __ldg(day + b);

    const __half* Arow = A  + (size_t)(b * TT + m0) * KDIM;
    const __half* Brow = Wt + ((size_t)d * NTOT + n0) * KDIM;

    const int lrow = tid >> 3;
    const int lchk = tid & 7;

    constexpr int KT = KDIM / 64;

    auto cp_part = [&](int s, int kt, int p) {
        const uint32_t as_ = sbase + s * STAGE_BYTES;
        const int row = p * 32 + lrow;
        const uint32_t soff = row * 128 + ((lchk ^ (row & 7)) << 4);
        const size_t goff = (size_t)kt * 64 + (size_t)row * KDIM + lchk * 8;
        cp16(as_ + soff,         Arow + goff);
        cp16(as_ + 16384 + soff, Brow + goff);
    };
    auto cp_stage = [&](int s, int kt) {
        #pragma unroll
        for (int p = 0; p < 4; p++) cp_part(s, kt, p);
        asm volatile("cp.async.commit_group;" ::: "memory");
    };

    const int lrow16 = lane & 15;
    const int lhi    = lane >> 4;
    auto load_afr = [&](uint32_t as_, int ks, uint32_t (*f)[4]) {
        const int chk = 2 * ks + lhi;
        #pragma unroll
        for (int mt = 0; mt < 4; mt++) {
            const int row = wm * 64 + mt * 16 + lrow16;
            ldm4(f[mt][0], f[mt][1], f[mt][2], f[mt][3],
                 as_ + row * 128 + (((row & 7) ^ chk) << 4));
        }
    };
    auto load_bfr = [&](uint32_t bs_, int ks, uint32_t (*f)[4]) {
        const int chk = 2 * ks + lhi;
        #pragma unroll
        for (int p = 0; p < 2; p++) {
            const int row = wn * 32 + p * 16 + lrow16;
            ldm4(f[p][0], f[p][1], f[p][2], f[p][3],
                 bs_ + row * 128 + (((row & 7) ^ chk) << 4));
        }
    };

    cp_stage(0, 0);
    cp_stage(1, 1);
    asm volatile("cp.async.wait_group 1;" ::: "memory");
    __syncthreads();

    float acc[4][4][4] = {};
    uint32_t af[2][4][4], bf[2][2][4];
    load_afr(sbase, 0, af[0]);
    load_bfr(sbase + 16384, 0, bf[0]);

    for (int i = 0; i < KT; i++) {
        const uint32_t as = sbase + (i % STAGES) * STAGE_BYTES;
        const uint32_t bs = as + 16384;
        const int inext = i + 2;
        const int snext = inext % STAGES;

        #pragma unroll
        for (int ks = 0; ks < 4; ks++) {
            const int cur = ks & 1, nxt = cur ^ 1;

            if (ks < 3) {
                load_afr(as, ks + 1, af[nxt]);
                load_bfr(bs, ks + 1, bf[nxt]);
            }
            if (inext < KT) cp_part(snext, inext, ks);

            if (ks == 2 && i + 1 < KT) {
                asm volatile("cp.async.wait_group 0;" ::: "memory");
                __syncthreads();
            }
            if (ks == 3) {
                if (inext < KT)
                    asm volatile("cp.async.commit_group;" ::: "memory");
                if (i + 1 < KT) {
                    const uint32_t as2 = sbase + ((i + 1) % STAGES) * STAGE_BYTES;
                    load_afr(as2, 0, af[nxt]);
                    load_bfr(as2 + 16384, 0, bf[nxt]);
                }
            }

            #pragma unroll
            for (int mt = 0; mt < 4; mt++)
                #pragma unroll
                for (int nt = 0; nt < 4; nt++)
                    mma16816(acc[mt][nt], af[cur][mt],
                             bf[cur][nt >> 1][nt & 1], bf[cur][nt >> 1][2 + (nt & 1)]);
        }
    }

    const int g   = lane >> 2;
    const int tig = lane & 3;
    const float* biasd = bias + (size_t)d * NTOT + n0 + wn * 32;
    CT* Cb = C + (size_t)(b * TT + m0 + wm * 64) * NTOT + n0 + wn * 32;

    #pragma unroll
    for (int nt = 0; nt < 4; nt++) {
        const int coff = nt * 8 + tig * 2;
        const float2 bb = *(const float2*)(biasd + coff);
        #pragma unroll
        for (int mt = 0; mt < 4; mt++) {
            const int r0 = mt * 16 + g;
            float2 v0, v1;
            v0.x = acc[mt][nt][0] + bb.x;  v0.y = acc[mt][nt][1] + bb.y;
            v1.x = acc[mt][nt][2] + bb.x;  v1.y = acc[mt][nt][3] + bb.y;
            if (RELU) {
                v0.x = fmaxf(v0.x, 0.0f); v0.y = fmaxf(v0.y, 0.0f);
                v1.x = fmaxf(v1.x, 0.0f); v1.y = fmaxf(v1.y, 0.0f);
            }
            if constexpr (sizeof(CT) == 2) {
                *(__half2*)((__half*)Cb + (size_t)r0 * NTOT + coff) =
                    __floats2half2_rn(v0.x, v0.y);
                *(__half2*)((__half*)Cb + (size_t)(r0 + 8) * NTOT + coff) =
                    __floats2half2_rn(v1.x, v1.y);
            } else {
                *(float2*)((float*)Cb + (size_t)r0 * NTOT + coff)       = v0;
                *(float2*)((float*)Cb + (size_t)(r0 + 8) * NTOT + coff) = v1;
            }
        }
    }
}

// ---------------------------------------------------------------- LayerNorm (= R9)
// One warp handles TWO consecutive rows; loads front-batched for MLP.
__global__ __launch_bounds__(256) void ln_kernel(
    float*       __restrict__ y,      // [B*T, D_OUT], in-place
    const float* __restrict__ gamma,
    const float* __restrict__ beta,
    const int*   __restrict__ day)
{
    const int w    = threadIdx.x >> 5;
    const int lane = threadIdx.x & 31;
    const int row0 = blockIdx.x * 16 + w * 2;
    const int b    = row0 >> 9;
    const int d    = __ldg(day + b);

    const float4* yr0 = (const float4*)(y + (size_t)row0 * DOUT);
    const float4* yr1 = (const float4*)(y + (size_t)(row0 + 1) * DOUT);

    float4 u[4], v[4];
    #pragma unroll
    for (int j = 0; j < 4; j++) u[j] = yr0[lane + 32 * j];
    #pragma unroll
    for (int j = 0; j < 4; j++) v[j] = yr1[lane + 32 * j];

    float s0 = 0.0f, q0 = 0.0f, s1 = 0.0f, q1 = 0.0f;
    #pragma unroll
    for (int j = 0; j < 4; j++) {
        s0 += u[j].x + u[j].y + u[j].z + u[j].w;
        q0 += u[j].x * u[j].x + u[j].y * u[j].y + u[j].z * u[j].z + u[j].w * u[j].w;
        s1 += v[j].x + v[j].y + v[j].z + v[j].w;
        q1 += v[j].x * v[j].x + v[j].y * v[j].y + v[j].z * v[j].z + v[j].w * v[j].w;
    }
    #pragma unroll
    for (int off = 16; off; off >>= 1) {
        s0 += __shfl_xor_sync(0xffffffffu, s0, off);
        q0 += __shfl_xor_sync(0xffffffffu, q0, off);
        s1 += __shfl_xor_sync(0xffffffffu, s1, off);
        q1 += __shfl_xor_sync(0xffffffffu, q1, off);
    }

    const float mean0 = s0 * (1.0f / DOUT);
    const float inv0  = rsqrtf(q0 * (1.0f / DOUT) - mean0 * mean0 + EPS_);
    const float mean1 = s1 * (1.0f / DOUT);
    const float inv1  = rsqrtf(q1 * (1.0f / DOUT) - mean1 * mean1 + EPS_);

    const float4* gp = (const float4*)(gamma + (size_t)d * DOUT);
    const float4* zp = (const float4*)(beta  + (size_t)d * DOUT);
    float4* yw0 = (float4*)(y + (size_t)row0 * DOUT);
    float4* yw1 = (float4*)(y + (size_t)(row0 + 1) * DOUT);

    #pragma unroll
    for (int j = 0; j < 4; j++) {
        const float4 gg = gp[lane + 32 * j];
        const float4 zz = zp[lane + 32 * j];
        float4 o0, o1;
        o0.x = (u[j].x - mean0) * inv0 * gg.x + zz.x;
        o0.y = (u[j].y - mean0) * inv0 * gg.y + zz.y;
        o0.z = (u[j].z - mean0) * inv0 * gg.z + zz.z;
        o0.w = (u[j].w - mean0) * inv0 * gg.w + zz.w;
        o1.x = (v[j].x - mean1) * inv1 * gg.x + zz.x;
        o1.y = (v[j].y - mean1) * inv1 * gg.y + zz.y;
        o1.z = (v[j].z - mean1) * inv1 * gg.z + zz.z;
        o1.w = (v[j].w - mean1) * inv1 * gg.w + zz.w;
        yw0[lane + 32 * j] = o0;
        yw1[lane + 32 * j] = o1;
    }
}

// ---------------------------------------------------------------- launch
extern "C" void kernel_launch(void* const* d_in, const int* in_sizes, int n_in,
                              void* d_out, int out_size)
{
    const float* x     = (const float*)d_in[0];
    const int*   day   = (const int*)  d_in[1];
    const float* W1    = (const float*)d_in[2];
    const float* b1    = (const float*)d_in[3];
    const float* W2    = (const float*)d_in[4];
    const float* b2    = (const float*)d_in[5];
    const float* gamma = (const float*)d_in[6];
    const float* beta  = (const float*)d_in[7];
    float* out = (float*)d_out;

    __half *xh, *h, *wt1, *wt2;
    cudaGetSymbolAddress((void**)&xh,  g_xh);
    cudaGetSymbolAddress((void**)&h,   g_h);
    cudaGetSymbolAddress((void**)&wt1, g_wt1);
    cudaGetSymbolAddress((void**)&wt2, g_wt2);

    prep_kernel<<<NBLK_X + NBLK_W1 + NBLK_W2, 256>>>(
        (const float4*)x, (__half2*)xh, W1, wt1, W2, wt2);

    cudaFuncSetAttribute(gemm_mma<DIN,  DHID, true,  __half>,
                         cudaFuncAttributeMaxDynamicSharedMemorySize, SMEM_DYN);
    cudaFuncSetAttribute(gemm_mma<DHID, DOUT, false, float>,
                         cudaFuncAttributeMaxDynamicSharedMemorySize, SMEM_DYN);

    gemm_mma<DIN,  DHID, true,  __half><<<dim3(BB, TT / 128, DHID / 128), 256, SMEM_DYN>>>(
        xh, wt1, b1, day, h);
    gemm_mma<DHID, DOUT, false, float><<<dim3(BB, TT / 128, DOUT / 128), 256, SMEM_DYN>>>(
        h, wt2, b2, day, out);

    ln_kernel<<<BB * TT / 16, 256>>>(out, gamma, beta, day);
}

// round 12
// speedup vs baseline: 1.0767x; 1.0032x over previous
#include <cuda_runtime.h>
#include <cuda_fp16.h>
#include <cstdint>

#define BB    64
#define TT    512
#define DIN   512
#define DHID  1024
#define DOUT  512
#define NDAYS 24
#define EPS_  1e-5f

// Scratch (__device__ globals; no runtime allocation).
__device__ __half g_xh [(size_t)BB * TT * DIN];       // 32 MB x -> fp16
__device__ __half g_h  [(size_t)BB * TT * DHID];      // 64 MB hidden fp16
__device__ __half g_wt1[(size_t)NDAYS * DHID * DIN];  // 24 MB W1^T [d][n][k] fp16
__device__ __half g_wt2[(size_t)NDAYS * DOUT * DHID]; // 24 MB W2^T [d][n][k] fp16

// ---------------------------------------------------------------- helpers
__device__ __forceinline__ uint32_t smem_u32(const void* p) {
    uint32_t a;
    asm("{ .reg .u64 t; cvta.to.shared.u64 t, %1; cvt.u32.u64 %0, t; }"
        : "=r"(a) : "l"(p));
    return a;
}
__device__ __forceinline__ void cp16(uint32_t dst, const void* src) {
    asm volatile("cp.async.cg.shared.global [%0], [%1], 16;"
                 :: "r"(dst), "l"(src) : "memory");
}
__device__ __forceinline__ void ldm4(uint32_t& r0, uint32_t& r1,
                                     uint32_t& r2, uint32_t& r3, uint32_t a) {
    asm volatile("ldmatrix.sync.aligned.m8n8.x4.shared.b16 {%0,%1,%2,%3}, [%4];"
                 : "=r"(r0), "=r"(r1), "=r"(r2), "=r"(r3) : "r"(a));
}
__device__ __forceinline__ void mma16816(float* c, const uint32_t* a,
                                         uint32_t b0, uint32_t b1) {
    asm volatile(
        "mma.sync.aligned.m16n8k16.row.col.f32.f16.f16.f32 "
        "{%0,%1,%2,%3}, {%4,%5,%6,%7}, {%8,%9}, {%0,%1,%2,%3};"
        : "+f"(c[0]), "+f"(c[1]), "+f"(c[2]), "+f"(c[3])
        : "r"(a[0]), "r"(a[1]), "r"(a[2]), "r"(a[3]), "r"(b0), "r"(b1));
}

// ---------------------------------------------------------------- fused prep
// Transpose 128(k) x 32(n) region of W [NDAYS][K][N] fp32 -> Wt [NDAYS][N][K]
// fp16.  Coarse tile: 16KB read (4 x float4/thread), 8KB write as uint4
// (8 fp16 along K per store, fully coalesced). Conflict-free smem.
template<int K, int N>
__device__ __forceinline__ void transpose_tile_wide(const float* __restrict__ W,
                                                    __half* __restrict__ Wt,
                                                    int d, int n0, int k0,
                                                    float (*t)[33], int tid) {
    const float* Wd  = W  + (size_t)d * K * N;
    __half*      Wtd = Wt + (size_t)d * N * K;

    // read: 128 k-rows x 32 n-cols = 1024 float4; 4 per thread, front-batched
    const int kr = tid >> 3;            // 0..31
    const int c  = (tid & 7) * 4;       // 0,4,..,28
    float4 v[4];
    #pragma unroll
    for (int g = 0; g < 4; g++)
        v[g] = *(const float4*)(Wd + (size_t)(k0 + g * 32 + kr) * N + n0 + c);
    #pragma unroll
    for (int g = 0; g < 4; g++) {
        const int k = g * 32 + kr;
        t[k][c + 0] = v[g].x; t[k][c + 1] = v[g].y;
        t[k][c + 2] = v[g].z; t[k][c + 3] = v[g].w;
    }
    __syncthreads();

    // write: 32 n-rows x 128 k = 512 uint4 chunks (8 fp16 each); 2 per thread
    #pragma unroll
    for (int p = 0; p < 2; p++) {
        const int cix = p * 256 + tid;
        const int n   = cix & 31;
        const int kc  = cix >> 5;       // 0..15
        const int kb  = kc * 8;
        __half2 h[4];
        #pragma unroll
        for (int i = 0; i < 4; i++)
            h[i] = __floats2half2_rn(t[kb + 2 * i][n], t[kb + 2 * i + 1][n]);
        uint4 o;
        o.x = *(uint32_t*)&h[0]; o.y = *(uint32_t*)&h[1];
        o.z = *(uint32_t*)&h[2]; o.w = *(uint32_t*)&h[3];
        *(uint4*)(Wtd + (size_t)(n0 + n) * K + k0 + kb) = o;
    }
}

#define NBLK_X  8192                       // (BB*TT*DIN/8)/256
#define NBLK_W1 ((DHID / 32) * (DIN / 128) * NDAYS)   // 32*4*24  = 3072
#define NBLK_W2 ((DOUT / 32) * (DHID / 128) * NDAYS)  // 16*8*24  = 3072

__global__ __launch_bounds__(256) void prep_kernel(
    const float4* __restrict__ x, __half2* __restrict__ xh,
    const float* __restrict__ W1, __half* __restrict__ wt1,
    const float* __restrict__ W2, __half* __restrict__ wt2)
{
    __shared__ float t[128][33];
    const int blk = blockIdx.x;
    const int tid = threadIdx.x;
    if (blk < NBLK_X) {
        const int i = blk * 256 + tid;
        float4 v0 = x[i * 2], v1 = x[i * 2 + 1];
        xh[i * 4 + 0] = __floats2half2_rn(v0.x, v0.y);
        xh[i * 4 + 1] = __floats2half2_rn(v0.z, v0.w);
        xh[i * 4 + 2] = __floats2half2_rn(v1.x, v1.y);
        xh[i * 4 + 3] = __floats2half2_rn(v1.z, v1.w);
    } else if (blk < NBLK_X + NBLK_W1) {
        int r = blk - NBLK_X;
        const int d = r / 128; r %= 128;          // 32 n-tiles x 4 k-tiles
        const int n0 = (r % 32) * 32;
        const int k0 = (r / 32) * 128;
        transpose_tile_wide<DIN, DHID>(W1, wt1, d, n0, k0, t, tid);
    } else {
        int r = blk - NBLK_X - NBLK_W1;
        const int d = r / 128; r %= 128;          // 16 n-tiles x 8 k-tiles
        const int n0 = (r % 16) * 32;
        const int k0 = (r / 16) * 128;
        transpose_tile_wide<DHID, DOUT>(W2, wt2, d, n0, k0, t, tid);
    }
}

// ---------------------------------------------------------------- FP16 GEMM (= R8)
// 256 threads, 8 warps 2(M) x 4(N); warp tile 64x32; K-chunk 64; 3 stages.
// Software-pipelined frags + spread cp.async; outer chunk loop kept ROLLED
// (full unroll blows I-cache — measured R9).
#define STAGES 3
#define STAGE_BYTES 32768
#define SMEM_DYN (STAGES * STAGE_BYTES)

template<int KDIM, int NTOT, bool RELU, typename CT>
__global__ __launch_bounds__(256, 2) void gemm_mma(
    const __half* __restrict__ A,
    const __half* __restrict__ Wt,
    const float*  __restrict__ bias,
    const int*    __restrict__ day,
    CT*           __restrict__ C)
{
    extern __shared__ char smem[];
    const uint32_t sbase = smem_u32(smem);

    const int tid  = threadIdx.x;
    const int lane = tid & 31;
    const int wid  = tid >> 5;
    const int wm   = wid & 1;
    const int wn   = wid >> 1;

    const int b  = blockIdx.x;
    const int m0 = blockIdx.y * 128;
    const int n0 = blockIdx.z * 128;
    const int d  = __ldg(day + b);

    const __half* Arow = A  + (size_t)(b * TT + m0) * KDIM;
    const __half* Brow = Wt + ((size_t)d * NTOT + n0) * KDIM;

    const int lrow = tid >> 3;
    const int lchk = tid & 7;

    constexpr int KT = KDIM / 64;

    auto cp_part = [&](int s, int kt, int p) {
        const uint32_t as_ = sbase + s * STAGE_BYTES;
        const int row = p * 32 + lrow;
        const uint32_t soff = row * 128 + ((lchk ^ (row & 7)) << 4);
        const size_t goff = (size_t)kt * 64 + (size_t)row * KDIM + lchk * 8;
        cp16(as_ + soff,         Arow + goff);
        cp16(as_ + 16384 + soff, Brow + goff);
    };
    auto cp_stage = [&](int s, int kt) {
        #pragma unroll
        for (int p = 0; p < 4; p++) cp_part(s, kt, p);
        asm volatile("cp.async.commit_group;" ::: "memory");
    };

    const int lrow16 = lane & 15;
    const int lhi    = lane >> 4;
    auto load_afr = [&](uint32_t as_, int ks, uint32_t (*f)[4]) {
        const int chk = 2 * ks + lhi;
        #pragma unroll
        for (int mt = 0; mt < 4; mt++) {
            const int row = wm * 64 + mt * 16 + lrow16;
            ldm4(f[mt][0], f[mt][1], f[mt][2], f[mt][3],
                 as_ + row * 128 + (((row & 7) ^ chk) << 4));
        }
    };
    auto load_bfr = [&](uint32_t bs_, int ks, uint32_t (*f)[4]) {
        const int chk = 2 * ks + lhi;
        #pragma unroll
        for (int p = 0; p < 2; p++) {
            const int row = wn * 32 + p * 16 + lrow16;
            ldm4(f[p][0], f[p][1], f[p][2], f[p][3],
                 bs_ + row * 128 + (((row & 7) ^ chk) << 4));
        }
    };

    cp_stage(0, 0);
    cp_stage(1, 1);
    asm volatile("cp.async.wait_group 1;" ::: "memory");
    __syncthreads();

    float acc[4][4][4] = {};
    uint32_t af[2][4][4], bf[2][2][4];
    load_afr(sbase, 0, af[0]);
    load_bfr(sbase + 16384, 0, bf[0]);

    for (int i = 0; i < KT; i++) {
        const uint32_t as = sbase + (i % STAGES) * STAGE_BYTES;
        const uint32_t bs = as + 16384;
        const int inext = i + 2;
        const int snext = inext % STAGES;

        #pragma unroll
        for (int ks = 0; ks < 4; ks++) {
            const int cur = ks & 1, nxt = cur ^ 1;

            if (ks < 3) {
                load_afr(as, ks + 1, af[nxt]);
                load_bfr(bs, ks + 1, bf[nxt]);
            }
            if (inext < KT) cp_part(snext, inext, ks);

            if (ks == 2 && i + 1 < KT) {
                asm volatile("cp.async.wait_group 0;" ::: "memory");
                __syncthreads();
            }
            if (ks == 3) {
                if (inext < KT)
                    asm volatile("cp.async.commit_group;" ::: "memory");
                if (i + 1 < KT) {
                    const uint32_t as2 = sbase + ((i + 1) % STAGES) * STAGE_BYTES;
                    load_afr(as2, 0, af[nxt]);
                    load_bfr(as2 + 16384, 0, bf[nxt]);
                }
            }

            #pragma unroll
            for (int mt = 0; mt < 4; mt++)
                #pragma unroll
                for (int nt = 0; nt < 4; nt++)
                    mma16816(acc[mt][nt], af[cur][mt],
                             bf[cur][nt >> 1][nt & 1], bf[cur][nt >> 1][2 + (nt & 1)]);
        }
    }

    const int g   = lane >> 2;
    const int tig = lane & 3;
    const float* biasd = bias + (size_t)d * NTOT + n0 + wn * 32;
    CT* Cb = C + (size_t)(b * TT + m0 + wm * 64) * NTOT + n0 + wn * 32;

    #pragma unroll
    for (int nt = 0; nt < 4; nt++) {
        const int coff = nt * 8 + tig * 2;
        const float2 bb = *(const float2*)(biasd + coff);
        #pragma unroll
        for (int mt = 0; mt < 4; mt++) {
            const int r0 = mt * 16 + g;
            float2 v0, v1;
            v0.x = acc[mt][nt][0] + bb.x;  v0.y = acc[mt][nt][1] + bb.y;
            v1.x = acc[mt][nt][2] + bb.x;  v1.y = acc[mt][nt][3] + bb.y;
            if (RELU) {
                v0.x = fmaxf(v0.x, 0.0f); v0.y = fmaxf(v0.y, 0.0f);
                v1.x = fmaxf(v1.x, 0.0f); v1.y = fmaxf(v1.y, 0.0f);
            }
            if constexpr (sizeof(CT) == 2) {
                *(__half2*)((__half*)Cb + (size_t)r0 * NTOT + coff) =
                    __floats2half2_rn(v0.x, v0.y);
                *(__half2*)((__half*)Cb + (size_t)(r0 + 8) * NTOT + coff) =
                    __floats2half2_rn(v1.x, v1.y);
            } else {
                *(float2*)((float*)Cb + (size_t)r0 * NTOT + coff)       = v0;
                *(float2*)((float*)Cb + (size_t)(r0 + 8) * NTOT + coff) = v1;
            }
        }
    }
}

// ---------------------------------------------------------------- LayerNorm (= R9)
__global__ __launch_bounds__(256) void ln_kernel(
    float*       __restrict__ y,      // [B*T, D_OUT], in-place
    const float* __restrict__ gamma,
    const float* __restrict__ beta,
    const int*   __restrict__ day)
{
    const int w    = threadIdx.x >> 5;
    const int lane = threadIdx.x & 31;
    const int row0 = blockIdx.x * 16 + w * 2;
    const int b    = row0 >> 9;
    const int d    = __ldg(day + b);

    const float4* yr0 = (const float4*)(y + (size_t)row0 * DOUT);
    const float4* yr1 = (const float4*)(y + (size_t)(row0 + 1) * DOUT);

    float4 u[4], v[4];
    #pragma unroll
    for (int j = 0; j < 4; j++) u[j] = yr0[lane + 32 * j];
    #pragma unroll
    for (int j = 0; j < 4; j++) v[j] = yr1[lane + 32 * j];

    float s0 = 0.0f, q0 = 0.0f, s1 = 0.0f, q1 = 0.0f;
    #pragma unroll
    for (int j = 0; j < 4; j++) {
        s0 += u[j].x + u[j].y + u[j].z + u[j].w;
        q0 += u[j].x * u[j].x + u[j].y * u[j].y + u[j].z * u[j].z + u[j].w * u[j].w;
        s1 += v[j].x + v[j].y + v[j].z + v[j].w;
        q1 += v[j].x * v[j].x + v[j].y * v[j].y + v[j].z * v[j].z + v[j].w * v[j].w;
    }
    #pragma unroll
    for (int off = 16; off; off >>= 1) {
        s0 += __shfl_xor_sync(0xffffffffu, s0, off);
        q0 += __shfl_xor_sync(0xffffffffu, q0, off);
        s1 += __shfl_xor_sync(0xffffffffu, s1, off);
        q1 += __shfl_xor_sync(0xffffffffu, q1, off);
    }

    const float mean0 = s0 * (1.0f / DOUT);
    const float inv0  = rsqrtf(q0 * (1.0f / DOUT) - mean0 * mean0 + EPS_);
    const float mean1 = s1 * (1.0f / DOUT);
    const float inv1  = rsqrtf(q1 * (1.0f / DOUT) - mean1 * mean1 + EPS_);

    const float4* gp = (const float4*)(gamma + (size_t)d * DOUT);
    const float4* zp = (const float4*)(beta  + (size_t)d * DOUT);
    float4* yw0 = (float4*)(y + (size_t)row0 * DOUT);
    float4* yw1 = (float4*)(y + (size_t)(row0 + 1) * DOUT);

    #pragma unroll
    for (int j = 0; j < 4; j++) {
        const float4 gg = gp[lane + 32 * j];
        const float4 zz = zp[lane + 32 * j];
        float4 o0, o1;
        o0.x = (u[j].x - mean0) * inv0 * gg.x + zz.x;
        o0.y = (u[j].y - mean0) * inv0 * gg.y + zz.y;
        o0.z = (u[j].z - mean0) * inv0 * gg.z + zz.z;
        o0.w = (u[j].w - mean0) * inv0 * gg.w + zz.w;
        o1.x = (v[j].x - mean1) * inv1 * gg.x + zz.x;
        o1.y = (v[j].y - mean1) * inv1 * gg.y + zz.y;
        o1.z = (v[j].z - mean1) * inv1 * gg.z + zz.z;
        o1.w = (v[j].w - mean1) * inv1 * gg.w + zz.w;
        yw0[lane + 32 * j] = o0;
        yw1[lane + 32 * j] = o1;
    }
}

// ---------------------------------------------------------------- launch
extern "C" void kernel_launch(void* const* d_in, const int* in_sizes, int n_in,
                              void* d_out, int out_size)
{
    const float* x     = (const float*)d_in[0];
    const int*   day   = (const int*)  d_in[1];
    const float* W1    = (const float*)d_in[2];
    const float* b1    = (const float*)d_in[3];
    const float* W2    = (const float*)d_in[4];
    const float* b2    = (const float*)d_in[5];
    const float* gamma = (const float*)d_in[6];
    const float* beta  = (const float*)d_in[7];
    float* out = (float*)d_out;

    __half *xh, *h, *wt1, *wt2;
    cudaGetSymbolAddress((void**)&xh,  g_xh);
    cudaGetSymbolAddress((void**)&h,   g_h);
    cudaGetSymbolAddress((void**)&wt1, g_wt1);
    cudaGetSymbolAddress((void**)&wt2, g_wt2);

    prep_kernel<<<NBLK_X + NBLK_W1 + NBLK_W2, 256>>>(
        (const float4*)x, (__half2*)xh, W1, wt1, W2, wt2);

    cudaFuncSetAttribute(gemm_mma<DIN,  DHID, true,  __half>,
                         cudaFuncAttributeMaxDynamicSharedMemorySize, SMEM_DYN);
    cudaFuncSetAttribute(gemm_mma<DHID, DOUT, false, float>,
                         cudaFuncAttributeMaxDynamicSharedMemorySize, SMEM_DYN);

    gemm_mma<DIN,  DHID, true,  __half><<<dim3(BB, TT / 128, DHID / 128), 256, SMEM_DYN>>>(
        xh, wt1, b1, day, h);
    gemm_mma<DHID, DOUT, false, float><<<dim3(BB, TT / 128, DOUT / 128), 256, SMEM_DYN>>>(
        h, wt2, b2, day, out);

    ln_kernel<<<BB * TT / 16, 256>>>(out, gamma, beta, day);
}